// round 1
// baseline (speedup 1.0000x reference)
#include <cuda_runtime.h>

// NeuralODE via exact linearity: x_k = (S^8)^k x0 with S the Tsit5 step matrix.
// Pure streaming kernel: read x0s (4MB), write trajs (104.9MB), coalesced via
// shared-memory staging.

namespace {

constexpr int TRAJ  = 25;
constexpr int NSUB  = 8;
constexpr int BLOCK = 128;

struct M2 { float a, b, c, d; };   // [a b; c d]

__device__ __forceinline__ M2 m2mul(const M2& x, const M2& y) {
    M2 r;
    r.a = fmaf(x.a, y.a, x.b * y.c);
    r.b = fmaf(x.a, y.b, x.b * y.d);
    r.c = fmaf(x.c, y.a, x.d * y.c);
    r.d = fmaf(x.c, y.b, x.d * y.d);
    return r;
}

// I + h * sum_i c[i] * K[i]
__device__ __forceinline__ M2 stageY(float h, const M2* K, const float* c, int n) {
    M2 r = {1.f, 0.f, 0.f, 1.f};
    for (int i = 0; i < n; ++i) {
        float s = h * c[i];
        r.a = fmaf(s, K[i].a, r.a);
        r.b = fmaf(s, K[i].b, r.b);
        r.c = fmaf(s, K[i].c, r.c);
        r.d = fmaf(s, K[i].d, r.d);
    }
    return r;
}

__global__ void __launch_bounds__(BLOCK)
ode_traj_kernel(const float* __restrict__ x0s,
                const float* __restrict__ matrix,
                const float* __restrict__ Tptr,
                float* __restrict__ out,
                int batch, long long out_elems, float tailval)
{
    __shared__ float  mats[TRAJ * 4];          // 400 B: Q^k for k=0..24
    __shared__ float2 stage[BLOCK * TRAJ];     // 25.6 KB output staging tile

    if (threadIdx.x == 0) {
        // --- Tsit5 tableau (Tsitouras 2011) ---
        const float A21 = 0.161f;
        const float A31 = -0.008480655492356989f, A32 = 0.335480655492357f;
        const float A41 = 2.8971530571054935f, A42 = -6.359448489975075f,
                    A43 = 4.3622954328695815f;
        const float A51 = 5.325864828439257f, A52 = -11.748883564062828f,
                    A53 = 7.4955393428898365f, A54 = -0.09249506636175525f;
        const float A61 = 5.86145544294642f, A62 = -12.92096931784711f,
                    A63 = 8.159367898576159f, A64 = -0.071584973281401f,
                    A65 = -0.028269050394068383f;
        const float B1 = 0.09646076681806523f, B2 = 0.01f,
                    B3 = 0.4798896504144996f, B4 = 1.379008574103742f,
                    B5 = -3.290069515436081f, B6 = 2.324710524099774f;

        const float h = 1.0f / float((TRAJ - 1) * NSUB);
        const float T = Tptr[0];
        M2 A = { T * matrix[0], T * matrix[1], T * matrix[2], T * matrix[3] };

        M2 K[6];
        K[0] = A;                                                   // k1 = A y
        { const float c[1] = {A21};                 K[1] = m2mul(A, stageY(h, K, c, 1)); }
        { const float c[2] = {A31, A32};            K[2] = m2mul(A, stageY(h, K, c, 2)); }
        { const float c[3] = {A41, A42, A43};       K[3] = m2mul(A, stageY(h, K, c, 3)); }
        { const float c[4] = {A51, A52, A53, A54};  K[4] = m2mul(A, stageY(h, K, c, 4)); }
        { const float c[5] = {A61, A62, A63, A64, A65}; K[5] = m2mul(A, stageY(h, K, c, 5)); }
        const float bb[6] = {B1, B2, B3, B4, B5, B6};
        M2 S = stageY(h, K, bb, 6);                 // one Tsit5 substep matrix

        M2 Q = m2mul(S, S); Q = m2mul(Q, Q); Q = m2mul(Q, Q);  // S^8: one save interval

        M2 P = {1.f, 0.f, 0.f, 1.f};                // Q^0
        #pragma unroll 1
        for (int k = 0; k < TRAJ; ++k) {
            mats[4 * k + 0] = P.a; mats[4 * k + 1] = P.b;
            mats[4 * k + 2] = P.c; mats[4 * k + 3] = P.d;
            P = m2mul(Q, P);
        }
    }
    __syncthreads();

    const int b = blockIdx.x * BLOCK + threadIdx.x;
    float2 xy = make_float2(0.f, 0.f);
    if (b < batch) xy = reinterpret_cast<const float2*>(x0s)[b];

    // Compute all 25 save points into the staging tile ([tid][k] == linear
    // order of the block's contiguous output region).
    #pragma unroll
    for (int k = 0; k < TRAJ; ++k) {
        float m0 = mats[4 * k + 0], m1 = mats[4 * k + 1];
        float m2 = mats[4 * k + 2], m3 = mats[4 * k + 3];
        stage[threadIdx.x * TRAJ + k] =
            make_float2(fmaf(m0, xy.x, m1 * xy.y), fmaf(m2, xy.x, m3 * xy.y));
    }
    __syncthreads();

    // Coalesced flush: block's output region is BLOCK*TRAJ contiguous float2s.
    const long long limit = (long long)batch * TRAJ;
    const long long base  = (long long)blockIdx.x * (BLOCK * TRAJ);
    float2* o2 = reinterpret_cast<float2*>(out);
    #pragma unroll
    for (int i = 0; i < TRAJ; ++i) {
        long long j = (long long)i * BLOCK + threadIdx.x;
        long long idx = base + j;
        if (idx < limit) o2[idx] = stage[j];
    }

    // Optional scalar tail (num_steps), exactly representable in fp32.
    if (blockIdx.x == 0 && threadIdx.x == 0) {
        for (long long i = (long long)batch * TRAJ * 2; i < out_elems; ++i)
            out[i] = tailval;
    }
}

} // namespace

extern "C" void kernel_launch(void* const* d_in, const int* in_sizes, int n_in,
                              void* d_out, int out_size) {
    const float* x0s    = (const float*)d_in[0];
    const float* matrix = (const float*)d_in[1];
    const float* T      = (const float*)d_in[2];
    float* out = (float*)d_out;

    const int batch = in_sizes[0] / 2;
    const int grid  = (batch + BLOCK - 1) / BLOCK;
    const float tail = (float)((long long)batch * (TRAJ - 1) * NSUB);

    ode_traj_kernel<<<grid, BLOCK>>>(x0s, matrix, T, out, batch,
                                     (long long)out_size, tail);
}